// round 16
// baseline (speedup 1.0000x reference)
#include <cuda_runtime.h>

#define BN   8192   // B*N rows
#define MPTS 2048   // M
#define EDIM 256
#define H1D  32
#define H2D  16

// scratch: 1/(2*sigma^2) per row  (device global — no allocs allowed)
__device__ float g_inv2s2[BN];

__device__ __forceinline__ float gelu_exact(float x) {
    return 0.5f * x * (1.0f + erff(x * 0.70710678118654752f));
}

// One warp per (b,n) row: 3-layer MLP -> sigma -> 1/(2 sigma^2)
__global__ __launch_bounds__(256) void sigma_kernel(
    const float* __restrict__ emb,
    const float* __restrict__ w1, const float* __restrict__ b1,
    const float* __restrict__ w2, const float* __restrict__ b2,
    const float* __restrict__ w3, const float* __restrict__ b3)
{
    const int warp = threadIdx.x >> 5;
    const int lane = threadIdx.x & 31;
    const int row  = blockIdx.x * 8 + warp;
    if (row >= BN) return;

    // ---- layer 1: h1[lane] = gelu( e . w1[:,lane] + b1[lane] ), lane = 0..31
    const float4* e4 = reinterpret_cast<const float4*>(emb + (size_t)row * EDIM);
    float a0 = __ldg(b1 + lane), a1 = 0.f, a2 = 0.f, a3 = 0.f;
    #pragma unroll 8
    for (int kk = 0; kk < EDIM / 4; kk++) {
        float4 ev = __ldg(e4 + kk);            // broadcast across lanes
        int k = kk * 4;
        a0 = fmaf(ev.x, __ldg(w1 + (k + 0) * H1D + lane), a0);
        a1 = fmaf(ev.y, __ldg(w1 + (k + 1) * H1D + lane), a1);
        a2 = fmaf(ev.z, __ldg(w1 + (k + 2) * H1D + lane), a2);
        a3 = fmaf(ev.w, __ldg(w1 + (k + 3) * H1D + lane), a3);
    }
    float h1 = gelu_exact((a0 + a1) + (a2 + a3));

    // ---- layer 2: h2[i] for lanes i = 0..15, via shuffle broadcast of h1
    float h2 = (lane < H2D) ? __ldg(b2 + lane) : 0.f;
    #pragma unroll
    for (int j = 0; j < H1D; j++) {
        float hv = __shfl_sync(0xffffffffu, h1, j);
        h2 = fmaf(hv, __ldg(w2 + j * H2D + (lane & 15)), h2);  // &15 keeps OOB lanes in-bounds
    }

    // ---- layer 3: scalar = sum_i gelu(h2[i]) * w3[i] + b3
    float p = 0.f;
    if (lane < H2D) p = gelu_exact(h2) * __ldg(w3 + lane);
    #pragma unroll
    for (int o = 16; o >= 1; o >>= 1) p += __shfl_xor_sync(0xffffffffu, p, o);

    if (lane == 0) {
        float s     = p + __ldg(b3);
        float sigm  = 1.f / (1.f + __expf(-s));
        float sigma = 0.1f + 9.9f * sigm;          // MIN + (MAX-MIN)*sigmoid
        g_inv2s2[row] = 1.f / (2.f * sigma * sigma);
    }
}

// One block per row: out[row, m] = exp(-((z[m]-mu[row])^2 sum) * inv2s2[row])
// 256 threads x 2 iters, float4 stores (4 m-values per store).
__global__ __launch_bounds__(256) void rbf_kernel(
    const float* __restrict__ z,
    const float* __restrict__ mu,
    float* __restrict__ out)
{
    const int row   = blockIdx.x;
    const float inv = g_inv2s2[row];
    const float2 muv = reinterpret_cast<const float2*>(mu)[row];

    const float4* z4 = reinterpret_cast<const float4*>(z);          // 2 m-points per float4
    float4* o4 = reinterpret_cast<float4*>(out + (size_t)row * MPTS);

    #pragma unroll
    for (int it = 0; it < 2; it++) {
        int i = threadIdx.x + it * 256;          // i in [0,512): covers m = 4i .. 4i+3
        float4 za = __ldg(z4 + 2 * i);
        float4 zb = __ldg(z4 + 2 * i + 1);
        float dx, dy;
        float4 r;
        dx = za.x - muv.x; dy = za.y - muv.y;
        r.x = __expf(-(fmaf(dx, dx, dy * dy)) * inv);
        dx = za.z - muv.x; dy = za.w - muv.y;
        r.y = __expf(-(fmaf(dx, dx, dy * dy)) * inv);
        dx = zb.x - muv.x; dy = zb.y - muv.y;
        r.z = __expf(-(fmaf(dx, dx, dy * dy)) * inv);
        dx = zb.z - muv.x; dy = zb.w - muv.y;
        r.w = __expf(-(fmaf(dx, dx, dy * dy)) * inv);
        o4[i] = r;
    }
}

extern "C" void kernel_launch(void* const* d_in, const int* in_sizes, int n_in,
                              void* d_out, int out_size)
{
    const float* z   = (const float*)d_in[0];  // [2048, 2]
    const float* mu  = (const float*)d_in[1];  // [8, 1024, 2]
    const float* emb = (const float*)d_in[2];  // [8, 1024, 256]
    const float* w1  = (const float*)d_in[3];  // [256, 32]
    const float* b1  = (const float*)d_in[4];  // [32]
    const float* w2  = (const float*)d_in[5];  // [32, 16]
    const float* b2  = (const float*)d_in[6];  // [16]
    const float* w3  = (const float*)d_in[7];  // [16, 1]
    const float* b3  = (const float*)d_in[8];  // [1]
    float* out = (float*)d_out;                // [8, 1024, 2048] fp32

    sigma_kernel<<<BN / 8, 256>>>(emb, w1, b1, w2, b2, w3, b3);
    rbf_kernel<<<BN, 256>>>(z, mu, out);
}

// round 17
// speedup vs baseline: 1.5631x; 1.5631x over previous
#include <cuda_runtime.h>

#define BN    8192   // B*N rows
#define MPTS  2048   // M
#define EDIM  256
#define H1D   32
#define H2D   16

// scratch: -log2(e)/(2*sigma^2) per row (device global; no allocs allowed)
__device__ float g_ninvl2[BN];

__device__ __forceinline__ float gelu_exact(float x) {
    return 0.5f * x * (1.0f + erff(x * 0.70710678118654752f));
}

__device__ __forceinline__ float ex2f_approx(float x) {
    float y;
    asm("ex2.approx.f32 %0, %1;" : "=f"(y) : "f"(x));
    return y;
}

// ============================================================================
// sigma kernel: 128 threads (4 warps) per block, 32 rows per block.
// lane = row. Each warp accumulates all 32 h1 columns for a 64-wide k-slice,
// w1 read as broadcast LDS.128. Partials reduced through smem (aliased onto
// the w1 tile to stay under the 48 KiB static-smem limit).
// ============================================================================
__global__ __launch_bounds__(128) void sigma_kernel(
    const float* __restrict__ emb,
    const float* __restrict__ w1, const float* __restrict__ b1,
    const float* __restrict__ w2, const float* __restrict__ b2,
    const float* __restrict__ w3, const float* __restrict__ b3)
{
    __shared__ __align__(16) float w1s[EDIM * H1D];     // 32 KiB; aliased as partial later
    __shared__ __align__(16) float w2s[H1D * H2D];      // 2 KiB
    __shared__ float b1s[H1D];
    __shared__ float b2s[H2D];
    __shared__ float w3s[H2D];
    __shared__ float b3s;

    const int tid  = threadIdx.x;
    const int warp = tid >> 5;     // 0..3 -> k slice
    const int lane = tid & 31;     // = local row
    const int row  = blockIdx.x * 32 + lane;

    // cooperative weight load
    {
        const float4* src = reinterpret_cast<const float4*>(w1);
        float4* dst = reinterpret_cast<float4*>(w1s);
        #pragma unroll
        for (int i = tid; i < EDIM * H1D / 4; i += 128) dst[i] = src[i];
        if (tid < H1D * H2D / 4)
            reinterpret_cast<float4*>(w2s)[tid] =
                reinterpret_cast<const float4*>(w2)[tid];
        if (tid < H1D) b1s[tid] = b1[tid];
        if (tid < H2D) { b2s[tid] = b2[tid]; w3s[tid] = w3[tid]; }
        if (tid == 0)  b3s = b3[0];
    }
    __syncthreads();

    // ---- layer 1 partial: k in [warp*64, warp*64+64), 32 col accumulators
    float acc[H1D];
    #pragma unroll
    for (int c = 0; c < H1D; c++) acc[c] = 0.f;

    const float4* e4 = reinterpret_cast<const float4*>(
        emb + (size_t)row * EDIM + warp * 64);

    #pragma unroll 4
    for (int kk = 0; kk < 16; kk++) {
        float4 ev = __ldg(e4 + kk);
        float ea[4] = {ev.x, ev.y, ev.z, ev.w};
        const float* wrow = w1s + (warp * 64 + kk * 4) * H1D;
        #pragma unroll
        for (int s = 0; s < 4; s++) {
            float e = ea[s];
            const float4* w4 = reinterpret_cast<const float4*>(wrow + s * H1D);
            #pragma unroll
            for (int c4 = 0; c4 < 8; c4++) {
                float4 wv = w4[c4];   // broadcast LDS.128
                acc[c4 * 4 + 0] = fmaf(e, wv.x, acc[c4 * 4 + 0]);
                acc[c4 * 4 + 1] = fmaf(e, wv.y, acc[c4 * 4 + 1]);
                acc[c4 * 4 + 2] = fmaf(e, wv.z, acc[c4 * 4 + 2]);
                acc[c4 * 4 + 3] = fmaf(e, wv.w, acc[c4 * 4 + 3]);
            }
        }
    }

    // all warps done reading w1s -> alias it as partial[4][32][36] (stride 36 avoids conflicts)
    __syncthreads();
    float* partial = w1s;                       // 4*32*36 = 4608 floats <= 8192
    {
        float* pr = partial + (warp * 32 + lane) * 36;
        #pragma unroll
        for (int c4 = 0; c4 < 8; c4++)
            *reinterpret_cast<float4*>(pr + c4 * 4) =
                make_float4(acc[c4*4+0], acc[c4*4+1], acc[c4*4+2], acc[c4*4+3]);
    }
    __syncthreads();

    // ---- tail: warp w owns rows [8w, 8w+8); lane = 8*g + rl;
    // group g handles h1 cols / layer-2 j-range [8g, 8g+8), reduced via shuffles.
    {
        const int g  = lane >> 3;       // 0..3
        const int rl = lane & 7;        // row-within-warp
        const int lr = warp * 8 + rl;   // local row 0..31

        float h1v[8];
        #pragma unroll
        for (int c4 = 0; c4 < 2; c4++) {
            int c = g * 8 + c4 * 4;
            float4 p0 = *reinterpret_cast<const float4*>(partial + (0 * 32 + lr) * 36 + c);
            float4 p1 = *reinterpret_cast<const float4*>(partial + (1 * 32 + lr) * 36 + c);
            float4 p2 = *reinterpret_cast<const float4*>(partial + (2 * 32 + lr) * 36 + c);
            float4 p3 = *reinterpret_cast<const float4*>(partial + (3 * 32 + lr) * 36 + c);
            h1v[c4*4+0] = gelu_exact(p0.x + p1.x + p2.x + p3.x + b1s[c + 0]);
            h1v[c4*4+1] = gelu_exact(p0.y + p1.y + p2.y + p3.y + b1s[c + 1]);
            h1v[c4*4+2] = gelu_exact(p0.z + p1.z + p2.z + p3.z + b1s[c + 2]);
            h1v[c4*4+3] = gelu_exact(p0.w + p1.w + p2.w + p3.w + b1s[c + 3]);
        }

        float h2[H2D];
        #pragma unroll
        for (int i = 0; i < H2D; i++) h2[i] = (g == 0) ? b2s[i] : 0.f;
        #pragma unroll
        for (int jj = 0; jj < 8; jj++) {
            int j = g * 8 + jj;
            float hv = h1v[jj];
            #pragma unroll
            for (int i = 0; i < H2D; i++)
                h2[i] = fmaf(hv, w2s[j * H2D + i], h2[i]);
        }
        #pragma unroll
        for (int i = 0; i < H2D; i++) {
            h2[i] += __shfl_xor_sync(0xffffffffu, h2[i], 8);
            h2[i] += __shfl_xor_sync(0xffffffffu, h2[i], 16);
        }

        if (g == 0) {
            float p = b3s;
            #pragma unroll
            for (int i = 0; i < H2D; i++)
                p = fmaf(gelu_exact(h2[i]), w3s[i], p);
            float sigm  = 1.f / (1.f + __expf(-p));
            float sigma = 0.1f + 9.9f * sigm;
            // fold -log2(e)/2 so rbf does a bare ex2
            g_ninvl2[blockIdx.x * 32 + lr] = -0.72134752044448170f / (sigma * sigma);
        }
    }
}

// ============================================================================
// rbf kernel: block owns RROWS rows x all 2048 m-points. z held in registers
// (8 points / thread), per row: 3 FFMA + 1 EX2 per point, 2 STG.128 per thread.
// ============================================================================
#define RROWS 16

__global__ __launch_bounds__(256) void rbf_kernel(
    const float* __restrict__ z,
    const float* __restrict__ mu,
    float* __restrict__ out)
{
    __shared__ float4 rowdat[RROWS];    // {mux, muy, ninvl2, -}
    const int tid   = threadIdx.x;
    const int rbase = blockIdx.x * RROWS;

    if (tid < RROWS) {
        float2 m = reinterpret_cast<const float2*>(mu)[rbase + tid];
        rowdat[tid] = make_float4(m.x, m.y, g_ninvl2[rbase + tid], 0.f);
    }

    // thread owns m-points 4*tid..4*tid+3 and 1024+4*tid..+3
    const float4* z4 = reinterpret_cast<const float4*>(z);
    float4 za = __ldg(z4 + 2 * tid);
    float4 zb = __ldg(z4 + 2 * tid + 1);
    float4 zc = __ldg(z4 + 512 + 2 * tid);
    float4 zd = __ldg(z4 + 513 + 2 * tid);

    float zx[8] = {za.x, za.z, zb.x, zb.z, zc.x, zc.z, zd.x, zd.z};
    float zy[8] = {za.y, za.w, zb.y, zb.w, zc.y, zc.w, zd.y, zd.w};
    float s[8];
    #pragma unroll
    for (int i = 0; i < 8; i++) s[i] = fmaf(zx[i], zx[i], zy[i] * zy[i]);

    __syncthreads();

    float4* o4 = reinterpret_cast<float4*>(out + (size_t)rbase * MPTS);

    #pragma unroll 4
    for (int r = 0; r < RROWS; r++) {
        float4 rd = rowdat[r];
        float n  = rd.z;                                   // -log2e/(2 sigma^2)
        float c0 = n * fmaf(rd.x, rd.x, rd.y * rd.y);      // n*|mu|^2
        float ax = -2.f * n * rd.x;
        float ay = -2.f * n * rd.y;

        float v[8];
        #pragma unroll
        for (int i = 0; i < 8; i++) {
            float t = fmaf(n, s[i], c0);
            t = fmaf(ax, zx[i], t);
            t = fmaf(ay, zy[i], t);
            v[i] = ex2f_approx(t);
        }
        float4* orow = o4 + r * (MPTS / 4);
        orow[tid]       = make_float4(v[0], v[1], v[2], v[3]);
        orow[256 + tid] = make_float4(v[4], v[5], v[6], v[7]);
    }
}

extern "C" void kernel_launch(void* const* d_in, const int* in_sizes, int n_in,
                              void* d_out, int out_size)
{
    const float* z   = (const float*)d_in[0];  // [2048, 2]
    const float* mu  = (const float*)d_in[1];  // [8, 1024, 2]
    const float* emb = (const float*)d_in[2];  // [8, 1024, 256]
    const float* w1  = (const float*)d_in[3];  // [256, 32]
    const float* b1  = (const float*)d_in[4];  // [32]
    const float* w2  = (const float*)d_in[5];  // [32, 16]
    const float* b2  = (const float*)d_in[6];  // [16]
    const float* w3  = (const float*)d_in[7];  // [16, 1]
    const float* b3  = (const float*)d_in[8];  // [1]
    float* out = (float*)d_out;                // [8, 1024, 2048] fp32

    sigma_kernel<<<BN / 32, 128>>>(emb, w1, b1, w2, b2, w3, b3);
    rbf_kernel<<<BN / RROWS, 256>>>(z, mu, out);
}